// round 11
// baseline (speedup 1.0000x reference)
#include <cuda_runtime.h>
#include <cstdint>

// Problem constants
#define Bn   4
#define Cn   16
#define Hn   800
#define Wn   1200
#define HWn  (Hn * Wn)          // 960000
#define HFn  200                 // H/4
#define WFn  200                 // W/6
#define NPIX (512 * 512)         // 262144

// Part -> source selection: parts {1, 14..21} come from source_feature
#define SRC_MASK 0x003FC002u
// Apparel classes: cls==2 or 15<=cls<=22  -> bits 2, 15..22
#define APP_MASK 0x007F8004u

// Packed decode bits
#define BIT_VALID   (1u << 20)
#define BIT_APPAREL (1u << 21)
#define BIT_BG      (1u << 22)
#define BIT_SRC     (1u << 23)
#define POS_MASK    0x000FFFFFu

// Scratch: one packed int per output pixel
__device__ unsigned int g_packed[(size_t)Bn * NPIX];   // 4.2 MB

// XLA lowering of (x*199)/255: divide -> multiply by fl(1/255) = 0x3B808081,
// multiplies NOT reassociated (verified bit-exact in R3).
__device__ __forceinline__ float recip255() {
    return __uint_as_float(0x3B808081u);
}

// ---------------------------------------------------------------------------
// Kernel 1: decode dense_pose once -> packed {pos, valid, apparel, bg, src}
// ---------------------------------------------------------------------------
__global__ __launch_bounds__(256) void k_decode(
    const float* __restrict__ dp)    // dense_pose [B,512,512,3]
{
    const int b   = blockIdx.y;
    const int pix = blockIdx.x * 256 + threadIdx.x;

    const float* d = dp + ((size_t)b * NPIX + pix) * 3;
    const float clsf = d[0];
    const float U    = d[1];
    const float V    = d[2];

    const int cls = (int)clsf;

    int p = cls - 1;
    p = p < 0 ? 0 : (p > 23 ? 23 : p);

    const float R = recip255();
    // XLA: t = RN(x*199); idx = trunc(RN(t * fl(1/255)))
    const int ui = (int)__fmul_rn(__fmul_rn(U, 199.0f), R);
    const int vi = (int)__fmul_rn(__fmul_rn(__fsub_rn(255.0f, V), 199.0f), R);

    const int tr  = p / 6;
    const int tc  = p - tr * 6;
    const unsigned int pos = (unsigned)((tr * HFn + ui) * Wn + (tc * WFn + vi));

    unsigned int packed = pos & POS_MASK;
    if ((cls >= 1) && (V != 0.0f))  packed |= BIT_VALID;
    if ((APP_MASK >> cls) & 1u)     packed |= BIT_APPAREL;
    if (cls != 0)                   packed |= BIT_BG;
    if ((SRC_MASK >> p) & 1u)       packed |= BIT_SRC;

    g_packed[(size_t)b * NPIX + pix] = packed;
}

// ---------------------------------------------------------------------------
// Kernel 2: channel-split gather.
//   gridDim.z = 5: z=0..3 feature groups (4 channels each, L2-resident
//   footprint per group), z=4 texture/composite group (channels 16..18).
//   Decode is a single coalesced 4B load per pixel.
// ---------------------------------------------------------------------------
__global__ __launch_bounds__(256) void k_split(
    const float* __restrict__ sf,    // source_feature [B,16,H,W]
    const float* __restrict__ tf,    // target_feature [B,16,H,W]
    const float* __restrict__ st,    // source_texture [B,3,H,W]
    const float* __restrict__ timg,  // target_image [B,3,512,512]
    float* __restrict__ out)         // [B,19,512,512]
{
    const int b   = blockIdx.y;
    const int g   = blockIdx.z;                      // 0..4
    const int pix = blockIdx.x * 256 + threadIdx.x;

    const unsigned int packed = g_packed[(size_t)b * NPIX + pix];
    const int  pos     = (int)(packed & POS_MASK);
    const bool valid   = packed & BIT_VALID;

    if (g < 4) {
        const bool use_src = packed & BIT_SRC;
        const int  ch0     = g * 4;
        const float* fbase = (use_src ? sf : tf)
                           + (size_t)b * Cn * HWn + (size_t)ch0 * HWn + pos;

        float v[4];
        if (valid) {
#pragma unroll
            for (int c = 0; c < 4; c++)
                v[c] = __ldg(fbase + (size_t)c * HWn);
        } else {
#pragma unroll
            for (int c = 0; c < 4; c++)
                v[c] = 0.0f;
        }

        float* ob = out + (size_t)b * 19 * NPIX + (size_t)ch0 * NPIX + pix;
#pragma unroll
        for (int c = 0; c < 4; c++)
            ob[(size_t)c * NPIX] = v[c];
    } else {
        const bool apparel = packed & BIT_APPAREL;
        const bool bg      = packed & BIT_BG;

        float* oc = out + (size_t)b * 19 * NPIX + 16 * NPIX + pix;
        if (apparel) {
            float t0 = 0.f, t1 = 0.f, t2 = 0.f;
            if (valid) {
                const float* tb = st + (size_t)b * 3 * HWn + pos;
                t0 = __ldg(tb);
                t1 = __ldg(tb + HWn);
                t2 = __ldg(tb + 2 * HWn);
            }
            oc[0 * NPIX] = t0;
            oc[1 * NPIX] = t1;
            oc[2 * NPIX] = t2;
        } else if (bg) {
            const float* ti = timg + (size_t)b * 3 * NPIX + pix;
            oc[0 * NPIX] = __ldg(ti);
            oc[1 * NPIX] = __ldg(ti + NPIX);
            oc[2 * NPIX] = __ldg(ti + 2 * NPIX);
        } else {
            oc[0 * NPIX] = 0.0f;
            oc[1 * NPIX] = 0.0f;
            oc[2 * NPIX] = 0.0f;
        }
    }
}

// ---------------------------------------------------------------------------
extern "C" void kernel_launch(void* const* d_in, const int* in_sizes, int n_in,
                              void* d_out, int out_size)
{
    const float* source_feature = (const float*)d_in[0];
    const float* target_feature = (const float*)d_in[1];
    const float* dense_pose     = (const float*)d_in[2];
    const float* source_texture = (const float*)d_in[3];
    const float* target_image   = (const float*)d_in[4];
    float* out = (float*)d_out;

    dim3 gD(NPIX / 256, Bn);
    k_decode<<<gD, 256>>>(dense_pose);

    dim3 gS(NPIX / 256, Bn, 5);
    k_split<<<gS, 256>>>(source_feature, target_feature,
                         source_texture, target_image, out);
}